// round 8
// baseline (speedup 1.0000x reference)
#include <cuda_runtime.h>
#include <math.h>

#define GD 60
#define GG 3600

__device__ float g_x[4096 * 96];   // features scratch (kernel A -> kernel B)

struct Params {
    const float* mv;
    const float* boxes;
    const float* W_stats; const float* b_stats; const float* g_stats; const float* be_stats;
    const float* W_b1;    const float* b_b1;    const float* g_b1;    const float* be_b1;
    const float* W_b2;    const float* b_b2;    const float* g_b2;    const float* be_b2;
    const float* W_ih;    const float* W_hh;    const float* b_ih;    const float* b_hh;
    const float* W_p1;    const float* b_p1;    const float* W_p2;    const float* b_p2;
    const float* W_s1;    const float* b_s1;    const float* W_s2;    const float* b_s2;
    const float* W_c1;    const float* b_c1;    const float* W_c2;    const float* b_c2;
    float* out;
};

__device__ __forceinline__ float tanhfast(float x) {
    float y;
    asm("tanh.approx.f32 %0, %1;" : "=f"(y) : "f"(x));
    return y;
}
__device__ __forceinline__ float sigfast(float x) {
    return fmaf(0.5f, tanhfast(0.5f * x), 0.5f);
}

union F4 { float4 f; unsigned long long u2[2]; };

__device__ __forceinline__ void ffma2(unsigned long long& d,
                                      const unsigned long long a,
                                      const unsigned long long b) {
    asm("fma.rn.f32x2 %0, %1, %2, %0;" : "+l"(d) : "l"(a), "l"(b));
}
__device__ __forceinline__ float red2(unsigned long long v) {
    float lo, hi;
    asm("mov.b64 {%0, %1}, %2;" : "=f"(lo), "=f"(hi) : "l"(v));
    return lo + hi;
}
__device__ __forceinline__ void cp16(float* dst, const float* src) {
    unsigned saddr = (unsigned)__cvta_generic_to_shared(dst);
    asm volatile("cp.async.cg.shared.global [%0], [%1], 16;" :: "r"(saddr), "l"(src));
}

// ===========================================================================
// Kernel A: per-box features (stats + MLPs + LayerNorms) -> g_x[4096][96]
// 256 CTAs x 256 thr; warp w handles boxes 16*blk + 2w, 2w+1. No block syncs.
// ===========================================================================
__global__ void __launch_bounds__(256)
features_kernel(Params p) {
    __shared__ float hwarp[16 * 32];

    const int tid  = threadIdx.x;
    const int lane = tid & 31;
    const int w    = tid >> 5;          // 0..7
    const int box0 = blockIdx.x * 16;
    const int b0 = 2 * w, b1 = 2 * w + 1;

    // hoisted per-lane weights
    const float* wsaP = p.W_stats + lane * 6;
    const float* wsbP = p.W_stats + (lane + 32) * 6;
    float ws_a[6], ws_b[6];
    #pragma unroll
    for (int k = 0; k < 6; k++) { ws_a[k] = __ldg(wsaP + k); ws_b[k] = __ldg(wsbP + k); }
    float bs_a  = __ldg(p.b_stats + lane),  bs_b  = __ldg(p.b_stats + lane + 32);
    float gs_a  = __ldg(p.g_stats + lane),  gs_b  = __ldg(p.g_stats + lane + 32);
    float bes_a = __ldg(p.be_stats + lane), bes_b = __ldg(p.be_stats + lane + 32);
    float4 wb1v = __ldg((const float4*)(p.W_b1) + lane);
    float bb1 = __ldg(p.b_b1 + lane), gb1 = __ldg(p.g_b1 + lane), beb1 = __ldg(p.be_b1 + lane);
    float bb2 = __ldg(p.b_b2 + lane), gb2 = __ldg(p.g_b2 + lane), beb2 = __ldg(p.be_b2 + lane);

    float4 bxA = __ldg((const float4*)p.boxes + (box0 + b0));
    float4 bxB = __ldg((const float4*)p.boxes + (box0 + b1));
    float anA0 = fminf(fmaxf(bxA.x * (1.0f / 960.0f), 0.0f), 1.0f);
    float anA1 = fminf(fmaxf(bxA.y * (1.0f / 960.0f), 0.0f), 1.0f);
    float anA2 = fminf(fmaxf(bxA.z * (1.0f / 960.0f), 0.0f), 1.0f);
    float anA3 = fminf(fmaxf(bxA.w * (1.0f / 960.0f), 0.0f), 1.0f);
    float anB0 = fminf(fmaxf(bxB.x * (1.0f / 960.0f), 0.0f), 1.0f);
    float anB1 = fminf(fmaxf(bxB.y * (1.0f / 960.0f), 0.0f), 1.0f);
    float anB2 = fminf(fmaxf(bxB.z * (1.0f / 960.0f), 0.0f), 1.0f);
    float anB3 = fminf(fmaxf(bxB.w * (1.0f / 960.0f), 0.0f), 1.0f);

    int xA1 = min(max((int)floorf(anA0 * 60.0f), 0), GD - 1);
    int yA1 = min(max((int)floorf(anA1 * 60.0f), 0), GD - 1);
    int xA2 = min(max((int)ceilf(anA2 * 60.0f), xA1 + 1), GD);
    int yA2 = min(max((int)ceilf(anA3 * 60.0f), yA1 + 1), GD);
    int xB1 = min(max((int)floorf(anB0 * 60.0f), 0), GD - 1);
    int yB1 = min(max((int)floorf(anB1 * 60.0f), 0), GD - 1);
    int xB2 = min(max((int)ceilf(anB2 * 60.0f), xB1 + 1), GD);
    int yB2 = min(max((int)ceilf(anB3 * 60.0f), yB1 + 1), GD);
    int wdA = xA2 - xA1, areaA = wdA * (yA2 - yA1);
    int wdB = xB2 - xB1, areaB = wdB * (yB2 - yB1);
    int maxArea = max(areaA, areaB);

    float sA0 = 0.f, sA1 = 0.f, qA0 = 0.f, qA1 = 0.f;
    float mxA0 = -1e30f, mxA1 = -1e30f, mnA0 = 1e30f, mnA1 = 1e30f;
    float sB0 = 0.f, sB1 = 0.f, qB0 = 0.f, qB1 = 0.f;
    float mxB0 = -1e30f, mxB1 = -1e30f, mnB0 = 1e30f, mnB1 = 1e30f;

    for (int c = lane; c < maxArea; c += 32) {
        if (c < areaA) {
            int ry = c / wdA;
            int idx = (yA1 + ry) * GD + xA1 + (c - ry * wdA);
            float v0 = __ldg(p.mv + idx);
            float v1 = __ldg(p.mv + GG + idx);
            sA0 += v0; qA0 += v0 * v0; mxA0 = fmaxf(mxA0, v0); mnA0 = fminf(mnA0, v0);
            sA1 += v1; qA1 += v1 * v1; mxA1 = fmaxf(mxA1, v1); mnA1 = fminf(mnA1, v1);
        }
        if (c < areaB) {
            int ry = c / wdB;
            int idx = (yB1 + ry) * GD + xB1 + (c - ry * wdB);
            float v0 = __ldg(p.mv + idx);
            float v1 = __ldg(p.mv + GG + idx);
            sB0 += v0; qB0 += v0 * v0; mxB0 = fmaxf(mxB0, v0); mnB0 = fminf(mnB0, v0);
            sB1 += v1; qB1 += v1 * v1; mxB1 = fmaxf(mxB1, v1); mnB1 = fminf(mnB1, v1);
        }
    }
    #pragma unroll
    for (int o = 16; o; o >>= 1) {
        sA0 += __shfl_xor_sync(0xffffffffu, sA0, o);
        sA1 += __shfl_xor_sync(0xffffffffu, sA1, o);
        qA0 += __shfl_xor_sync(0xffffffffu, qA0, o);
        qA1 += __shfl_xor_sync(0xffffffffu, qA1, o);
        sB0 += __shfl_xor_sync(0xffffffffu, sB0, o);
        sB1 += __shfl_xor_sync(0xffffffffu, sB1, o);
        qB0 += __shfl_xor_sync(0xffffffffu, qB0, o);
        qB1 += __shfl_xor_sync(0xffffffffu, qB1, o);
        mxA0 = fmaxf(mxA0, __shfl_xor_sync(0xffffffffu, mxA0, o));
        mxA1 = fmaxf(mxA1, __shfl_xor_sync(0xffffffffu, mxA1, o));
        mnA0 = fminf(mnA0, __shfl_xor_sync(0xffffffffu, mnA0, o));
        mnA1 = fminf(mnA1, __shfl_xor_sync(0xffffffffu, mnA1, o));
        mxB0 = fmaxf(mxB0, __shfl_xor_sync(0xffffffffu, mxB0, o));
        mxB1 = fmaxf(mxB1, __shfl_xor_sync(0xffffffffu, mxB1, o));
        mnB0 = fminf(mnB0, __shfl_xor_sync(0xffffffffu, mnB0, o));
        mnB1 = fminf(mnB1, __shfl_xor_sync(0xffffffffu, mnB1, o));
    }
    float rcA = __fdividef(1.0f, (float)areaA);
    float rcB = __fdividef(1.0f, (float)areaB);
    float mA0 = sA0 * rcA, mA1 = sA1 * rcA;
    float mB0 = sB0 * rcB, mB1 = sB1 * rcB;
    float stA[6], stB[6];
    stA[0] = mA0; stA[1] = mA1;
    stA[2] = sqrtf(fmaxf(qA0 * rcA - mA0 * mA0, 0.0f));
    stA[3] = sqrtf(fmaxf(qA1 * rcA - mA1 * mA1, 0.0f));
    stA[4] = mxA0 - mnA0; stA[5] = mxA1 - mnA1;
    stB[0] = mB0; stB[1] = mB1;
    stB[2] = sqrtf(fmaxf(qB0 * rcB - mB0 * mB0, 0.0f));
    stB[3] = sqrtf(fmaxf(qB1 * rcB - mB1 * mB1, 0.0f));
    stB[4] = mxB0 - mnB0; stB[5] = mxB1 - mnB1;

    float* gxA = g_x + (box0 + b0) * 96;
    float* gxB = g_x + (box0 + b1) * 96;

    float zAa = bs_a, zAb = bs_b, zBa = bs_a, zBb = bs_b;
    #pragma unroll
    for (int k = 0; k < 6; k++) {
        zAa = fmaf(stA[k], ws_a[k], zAa);
        zAb = fmaf(stA[k], ws_b[k], zAb);
        zBa = fmaf(stB[k], ws_a[k], zBa);
        zBb = fmaf(stB[k], ws_b[k], zBb);
    }
    {
        float sA = zAa + zAb, qA = zAa * zAa + zAb * zAb;
        float sB = zBa + zBb, qB = zBa * zBa + zBb * zBb;
        #pragma unroll
        for (int o = 16; o; o >>= 1) {
            sA += __shfl_xor_sync(0xffffffffu, sA, o);
            qA += __shfl_xor_sync(0xffffffffu, qA, o);
            sB += __shfl_xor_sync(0xffffffffu, sB, o);
            qB += __shfl_xor_sync(0xffffffffu, qB, o);
        }
        float muA = sA * (1.0f / 64.0f);
        float invA = rsqrtf(fmaxf(qA * (1.0f / 64.0f) - muA * muA, 0.0f) + 1e-5f);
        float muB = sB * (1.0f / 64.0f);
        float invB = rsqrtf(fmaxf(qB * (1.0f / 64.0f) - muB * muB, 0.0f) + 1e-5f);
        gxA[lane]      = fmaxf(fmaf((zAa - muA) * invA, gs_a, bes_a), 0.0f);
        gxA[32 + lane] = fmaxf(fmaf((zAb - muA) * invA, gs_b, bes_b), 0.0f);
        gxB[lane]      = fmaxf(fmaf((zBa - muB) * invB, gs_a, bes_a), 0.0f);
        gxB[32 + lane] = fmaxf(fmaf((zBb - muB) * invB, gs_b, bes_b), 0.0f);
    }

    float tA = bb1, tB = bb1;
    tA = fmaf(anA0, wb1v.x, tA); tB = fmaf(anB0, wb1v.x, tB);
    tA = fmaf(anA1, wb1v.y, tA); tB = fmaf(anB1, wb1v.y, tB);
    tA = fmaf(anA2, wb1v.z, tA); tB = fmaf(anB2, wb1v.z, tB);
    tA = fmaf(anA3, wb1v.w, tA); tB = fmaf(anB3, wb1v.w, tB);
    {
        float sA = tA, qA = tA * tA, sB = tB, qB = tB * tB;
        #pragma unroll
        for (int o = 16; o; o >>= 1) {
            sA += __shfl_xor_sync(0xffffffffu, sA, o);
            qA += __shfl_xor_sync(0xffffffffu, qA, o);
            sB += __shfl_xor_sync(0xffffffffu, sB, o);
            qB += __shfl_xor_sync(0xffffffffu, qB, o);
        }
        float muA = sA * (1.0f / 32.0f);
        float invA = rsqrtf(fmaxf(qA * (1.0f / 32.0f) - muA * muA, 0.0f) + 1e-5f);
        float muB = sB * (1.0f / 32.0f);
        float invB = rsqrtf(fmaxf(qB * (1.0f / 32.0f) - muB * muB, 0.0f) + 1e-5f);
        hwarp[b0 * 32 + lane] = fmaxf(fmaf((tA - muA) * invA, gb1, beb1), 0.0f);
        hwarp[b1 * 32 + lane] = fmaxf(fmaf((tB - muB) * invB, gb1, beb1), 0.0f);
    }
    __syncwarp();
    float tA0 = bb2, tA1 = 0.0f, tB0 = bb2, tB1 = 0.0f;
    const float* wb2 = p.W_b2 + lane * 32;
    #pragma unroll
    for (int k4 = 0; k4 < 8; k4 += 2) {
        float4 wva = __ldg((const float4*)wb2 + k4);
        float4 wvb = __ldg((const float4*)wb2 + k4 + 1);
        const float* hpA = hwarp + b0 * 32 + 4 * k4;
        const float* hpB = hwarp + b1 * 32 + 4 * k4;
        tA0 = fmaf(hpA[0], wva.x, tA0); tB0 = fmaf(hpB[0], wva.x, tB0);
        tA0 = fmaf(hpA[1], wva.y, tA0); tB0 = fmaf(hpB[1], wva.y, tB0);
        tA0 = fmaf(hpA[2], wva.z, tA0); tB0 = fmaf(hpB[2], wva.z, tB0);
        tA0 = fmaf(hpA[3], wva.w, tA0); tB0 = fmaf(hpB[3], wva.w, tB0);
        tA1 = fmaf(hpA[4], wvb.x, tA1); tB1 = fmaf(hpB[4], wvb.x, tB1);
        tA1 = fmaf(hpA[5], wvb.y, tA1); tB1 = fmaf(hpB[5], wvb.y, tB1);
        tA1 = fmaf(hpA[6], wvb.z, tA1); tB1 = fmaf(hpB[6], wvb.z, tB1);
        tA1 = fmaf(hpA[7], wvb.w, tA1); tB1 = fmaf(hpB[7], wvb.w, tB1);
    }
    __syncwarp();
    {
        float t2A = tA0 + tA1, t2B = tB0 + tB1;
        float sA = t2A, qA = t2A * t2A, sB = t2B, qB = t2B * t2B;
        #pragma unroll
        for (int o = 16; o; o >>= 1) {
            sA += __shfl_xor_sync(0xffffffffu, sA, o);
            qA += __shfl_xor_sync(0xffffffffu, qA, o);
            sB += __shfl_xor_sync(0xffffffffu, sB, o);
            qB += __shfl_xor_sync(0xffffffffu, qB, o);
        }
        float muA = sA * (1.0f / 32.0f);
        float invA = rsqrtf(fmaxf(qA * (1.0f / 32.0f) - muA * muA, 0.0f) + 1e-5f);
        float muB = sB * (1.0f / 32.0f);
        float invB = rsqrtf(fmaxf(qB * (1.0f / 32.0f) - muB * muB, 0.0f) + 1e-5f);
        gxA[64 + lane] = fmaxf(fmaf((t2A - muA) * invA, gb2, beb2), 0.0f);
        gxB[64 + lane] = fmaxf(fmaf((t2B - muB) * invB, gb2, beb2), 0.0f);
    }
}

// ===========================================================================
// Kernel B: gates GEMM + LSTM + heads + decode. grid 128 x 512 thr.
// smem: x_s[32*96]=3072 | wbuf 38400 | big 10400  (207 KB, same as R5)
// ===========================================================================
#define NT 512
#define XS_OFF  0
#define WB_OFF  3072
#define BIG_OFF 41472
#define SCR_OFF (WB_OFF + 25600)
#define SMEM_BYTES (51872 * 4)

__global__ void __launch_bounds__(NT, 1)
gemm_kernel(Params p) {
    extern __shared__ float smem[];
    float* x_s  = smem + XS_OFF;
    float* wbuf = smem + WB_OFF;
    float* big  = smem + BIG_OFF;
    float* scr  = smem + SCR_OFF;

    float* h_s   = big;              // [32][128]
    float* hid_s = big + 4096;       // [32][192]
    float* fin_s = big + 10240;      // 160

    const int tid  = threadIdx.x;
    const int lane = tid & 31;
    const int w    = tid >> 5;       // 0..15
    const int box0 = blockIdx.x * 32;

    // ---- stage W_ih tile (f-gate skipped) + x tile in one group ----
    #pragma unroll
    for (int it = 0; it < 18; it++) {
        int idx = tid + it * NT;
        int n = idx / 24, k4 = idx % 24;
        int row = (n < 128) ? n : n + 128;
        cp16(wbuf + n * 100 + 4 * k4, p.W_ih + row * 96 + 4 * k4);
    }
    #pragma unroll
    for (int it = 0; it < 2; it++) {
        int idx = tid + it * NT;
        if (idx < 768) cp16(x_s + 4 * idx, g_x + box0 * 96 + 4 * idx);
    }
    asm volatile("cp.async.commit_group;");

    // bias loads off the critical path
    const int cg = w & 3;
    const int bg = w >> 2;
    const int hu = lane + 32 * cg;
    float bi  = __ldg(p.b_ih + hu)       + __ldg(p.b_hh + hu);
    float bgv = __ldg(p.b_ih + 256 + hu) + __ldg(p.b_hh + 256 + hu);
    float bo  = __ldg(p.b_ih + 384 + hu) + __ldg(p.b_hh + 384 + hu);

    asm volatile("cp.async.wait_group 0;");
    __syncthreads();

    // ---- gates GEMM (f32x2, k-paired) ----
    unsigned long long acc[8][3];
    #pragma unroll
    for (int m = 0; m < 8; m++)
        #pragma unroll
        for (int u = 0; u < 3; u++) acc[m][u] = 0ull;

    {
        const int wr0 = hu * 100;
        const int wr1 = (hu + 128) * 100;
        const int wr2 = (hu + 256) * 100;
        const float* xb = x_s + (8 * bg) * 96;

        #pragma unroll 4
        for (int k4 = 0; k4 < 24; k4++) {
            F4 wv0, wv1, wv2;
            wv0.f = *(const float4*)(wbuf + wr0 + 4 * k4);
            wv1.f = *(const float4*)(wbuf + wr1 + 4 * k4);
            wv2.f = *(const float4*)(wbuf + wr2 + 4 * k4);
            #pragma unroll
            for (int m = 0; m < 8; m++) {
                F4 xv;
                xv.f = *(const float4*)(xb + m * 96 + 4 * k4);
                ffma2(acc[m][0], xv.u2[0], wv0.u2[0]);
                ffma2(acc[m][0], xv.u2[1], wv0.u2[1]);
                ffma2(acc[m][1], xv.u2[0], wv1.u2[0]);
                ffma2(acc[m][1], xv.u2[1], wv1.u2[1]);
                ffma2(acc[m][2], xv.u2[0], wv2.u2[0]);
                ffma2(acc[m][2], xv.u2[1], wv2.u2[1]);
            }
        }
    }
    __syncthreads();   // all wbuf reads done before heads restage

    // ---- stage heads weights (overlap with LSTM) ----
    #pragma unroll
    for (int it = 0; it < 12; it++) {
        int idx = tid + it * NT;
        int n = idx >> 5, k4 = idx & 31;
        const float* src = (n < 64) ? (p.W_p1 + n * 128)
                         : (n < 128) ? (p.W_s1 + (n - 64) * 128)
                                     : (p.W_c1 + (n - 128) * 128);
        cp16(wbuf + n * 132 + 4 * k4, src + 4 * k4);
    }
    asm volatile("cp.async.commit_group;");

    // ---- LSTM in registers (h0=c0=0) ----
    #pragma unroll
    for (int m = 0; m < 8; m++) {
        float iv = red2(acc[m][0]) + bi;
        float gv = red2(acc[m][1]) + bgv;
        float ov = red2(acc[m][2]) + bo;
        float c = sigfast(iv) * tanhfast(gv);
        h_s[(8 * bg + m) * 128 + hu] = sigfast(ov) * tanhfast(c);
    }

    asm volatile("cp.async.wait_group 0;");
    __syncthreads();

    // ---- heads GEMM (f32x2, k-split across warp halves) ----
    const int kh  = w >> 3;
    const int cg2 = (w & 7) & 1;
    const int bg2 = (w & 7) >> 1;

    unsigned long long acc2[8][3];
    #pragma unroll
    for (int m = 0; m < 8; m++)
        #pragma unroll
        for (int u = 0; u < 3; u++) acc2[m][u] = 0ull;

    {
        int wr[3];
        #pragma unroll
        for (int u = 0; u < 3; u++) wr[u] = (lane + 32 * (3 * cg2 + u)) * 132;
        const float* hb = h_s + (8 * bg2) * 128;
        const int k40 = kh * 16;

        #pragma unroll 4
        for (int kk = 0; kk < 16; kk++) {
            int k4 = k40 + kk;
            F4 wv0, wv1, wv2;
            wv0.f = *(const float4*)(wbuf + wr[0] + 4 * k4);
            wv1.f = *(const float4*)(wbuf + wr[1] + 4 * k4);
            wv2.f = *(const float4*)(wbuf + wr[2] + 4 * k4);
            #pragma unroll
            for (int m = 0; m < 8; m++) {
                F4 hv;
                hv.f = *(const float4*)(hb + m * 128 + 4 * k4);
                ffma2(acc2[m][0], hv.u2[0], wv0.u2[0]);
                ffma2(acc2[m][0], hv.u2[1], wv0.u2[1]);
                ffma2(acc2[m][1], hv.u2[0], wv1.u2[0]);
                ffma2(acc2[m][1], hv.u2[1], wv1.u2[1]);
                ffma2(acc2[m][2], hv.u2[0], wv2.u2[0]);
                ffma2(acc2[m][2], hv.u2[1], wv2.u2[1]);
            }
        }
    }

    float ar[8][3];
    #pragma unroll
    for (int m = 0; m < 8; m++)
        #pragma unroll
        for (int u = 0; u < 3; u++) ar[m][u] = red2(acc2[m][u]);

    const int sbase = (((bg2 * 2 + cg2) * 32) + lane) * 24;
    if (kh == 1) {
        #pragma unroll
        for (int m = 0; m < 8; m++)
            #pragma unroll
            for (int u = 0; u < 3; u++) scr[sbase + m * 3 + u] = ar[m][u];
    }
    __syncthreads();
    if (kh == 0) {
        #pragma unroll
        for (int u = 0; u < 3; u++) {
            int n = lane + 32 * (3 * cg2 + u);
            float bias = (n < 64) ? __ldg(p.b_p1 + n)
                       : (n < 128) ? __ldg(p.b_s1 + n - 64)
                                   : __ldg(p.b_c1 + n - 128);
            #pragma unroll
            for (int m = 0; m < 8; m++)
                hid_s[(8 * bg2 + m) * 192 + n] =
                    fmaxf(ar[m][u] + scr[sbase + m * 3 + u] + bias, 0.0f);
        }
    }
    __syncthreads();

    // ---- head second layers ----
    if (tid < 160) {
        int b = tid / 5, o = tid % 5;
        const float* hp = hid_s + b * 192 + ((o < 2) ? 0 : (o < 4) ? 64 : 128);
        const float* wp;
        float a;
        if (o == 0)      { wp = p.W_p2;      a = __ldg(p.b_p2); }
        else if (o == 1) { wp = p.W_p2 + 64; a = __ldg(p.b_p2 + 1); }
        else if (o == 2) { wp = p.W_s2;      a = __ldg(p.b_s2); }
        else if (o == 3) { wp = p.W_s2 + 64; a = __ldg(p.b_s2 + 1); }
        else             { wp = p.W_c2;      a = __ldg(p.b_c2); }
        #pragma unroll
        for (int k4 = 0; k4 < 16; k4++) {
            float4 hv = *(const float4*)(hp + 4 * k4);
            float4 wv = __ldg((const float4*)wp + k4);
            a = fmaf(hv.x, wv.x, a);
            a = fmaf(hv.y, wv.y, a);
            a = fmaf(hv.z, wv.z, a);
            a = fmaf(hv.w, wv.w, a);
        }
        fin_s[b * 5 + o] = a;
    }
    __syncthreads();

    // ---- decode + output ----
    if (tid < 32) {
        int b = tid;
        float4 bx = __ldg((const float4*)p.boxes + (box0 + b));
        float cx = (bx.x + bx.z) * 0.5f, cy = (bx.y + bx.w) * 0.5f;
        float wd = bx.z - bx.x, hg = bx.w - bx.y;
        float ncx = cx + fin_s[b * 5 + 0];
        float ncy = cy + fin_s[b * 5 + 1];
        float nw = wd * __expf(fin_s[b * 5 + 2]);
        float nh = hg * __expf(fin_s[b * 5 + 3]);
        float conf = __fdividef(1.0f, 1.0f + __expf(-fin_s[b * 5 + 4]));
        float* op = p.out + (box0 + b) * 5;
        op[0] = ncx - nw * 0.5f;
        op[1] = ncy - nh * 0.5f;
        op[2] = ncx + nw * 0.5f;
        op[3] = ncy + nh * 0.5f;
        op[4] = conf;
    }
}

extern "C" void kernel_launch(void* const* d_in, const int* in_sizes, int n_in,
                              void* d_out, int out_size) {
    (void)in_sizes; (void)n_in; (void)out_size;
    Params p;
    p.mv       = (const float*)d_in[0];
    p.boxes    = (const float*)d_in[1];
    p.W_stats  = (const float*)d_in[2];
    p.b_stats  = (const float*)d_in[3];
    p.g_stats  = (const float*)d_in[4];
    p.be_stats = (const float*)d_in[5];
    p.W_b1     = (const float*)d_in[6];
    p.b_b1     = (const float*)d_in[7];
    p.g_b1     = (const float*)d_in[8];
    p.be_b1    = (const float*)d_in[9];
    p.W_b2     = (const float*)d_in[10];
    p.b_b2     = (const float*)d_in[11];
    p.g_b2     = (const float*)d_in[12];
    p.be_b2    = (const float*)d_in[13];
    p.W_ih     = (const float*)d_in[14];
    p.W_hh     = (const float*)d_in[15];
    p.b_ih     = (const float*)d_in[16];
    p.b_hh     = (const float*)d_in[17];
    p.W_p1     = (const float*)d_in[18];
    p.b_p1     = (const float*)d_in[19];
    p.W_p2     = (const float*)d_in[20];
    p.b_p2     = (const float*)d_in[21];
    p.W_s1     = (const float*)d_in[22];
    p.b_s1     = (const float*)d_in[23];
    p.W_s2     = (const float*)d_in[24];
    p.b_s2     = (const float*)d_in[25];
    p.W_c1     = (const float*)d_in[26];
    p.b_c1     = (const float*)d_in[27];
    p.W_c2     = (const float*)d_in[28];
    p.b_c2     = (const float*)d_in[29];
    p.out      = (float*)d_out;

    features_kernel<<<256, 256>>>(p);
    cudaFuncSetAttribute(gemm_kernel,
                         cudaFuncAttributeMaxDynamicSharedMemorySize, SMEM_BYTES);
    gemm_kernel<<<128, NT, SMEM_BYTES>>>(p);
}

// round 9
// speedup vs baseline: 1.4272x; 1.4272x over previous
#include <cuda_runtime.h>
#include <math.h>
#include <stdint.h>

#define GD 60
#define GG 3600
#define NT 512

// shared memory layout (floats):
//   x_s    @ 0      : 32*100 = 3200      (tf32 bits)
//   wbuf   @ 3200   : 38400              (gates W [384*100] tf32; later heads W [192*132] in [0,25344))
//   gates_s = wbuf + 25600 : 32*388 = 12416 (fp32 gate pre-activations; overlays dead o-gate rows)
//   h_s    @ 41600  : 32*132 = 4224      (tf32 bits; phase-A hwarp overlays first 1024)
//   hid_s  @ 45824  : 32*196 = 6272      (fp32)
//   fin    @ 52096  : 160
#define XS_OFF   0
#define WB_OFF   3200
#define GS_OFF   (WB_OFF + 25600)
#define HS_OFF   41600
#define HID_OFF  45824
#define FIN_OFF  52096
#define SMEM_FLOATS 52256
#define SMEM_BYTES (SMEM_FLOATS * 4)

struct Params {
    const float* mv;
    const float* boxes;
    const float* W_stats; const float* b_stats; const float* g_stats; const float* be_stats;
    const float* W_b1;    const float* b_b1;    const float* g_b1;    const float* be_b1;
    const float* W_b2;    const float* b_b2;    const float* g_b2;    const float* be_b2;
    const float* W_ih;    const float* W_hh;    const float* b_ih;    const float* b_hh;
    const float* W_p1;    const float* b_p1;    const float* W_p2;    const float* b_p2;
    const float* W_s1;    const float* b_s1;    const float* W_s2;    const float* b_s2;
    const float* W_c1;    const float* b_c1;    const float* W_c2;    const float* b_c2;
    float* out;
};

__device__ __forceinline__ float tanhfast(float x) {
    float y;
    asm("tanh.approx.f32 %0, %1;" : "=f"(y) : "f"(x));
    return y;
}
__device__ __forceinline__ float sigfast(float x) {
    return fmaf(0.5f, tanhfast(0.5f * x), 0.5f);
}
__device__ __forceinline__ uint32_t tf32cvt(float x) {
    uint32_t r;
    asm("cvt.rna.tf32.f32 %0, %1;" : "=r"(r) : "f"(x));
    return r;
}
__device__ __forceinline__ void mma_tf32(float* d,
                                         uint32_t a0, uint32_t a1, uint32_t a2, uint32_t a3,
                                         uint32_t b0, uint32_t b1) {
    asm volatile(
        "mma.sync.aligned.m16n8k8.row.col.f32.tf32.tf32.f32 "
        "{%0,%1,%2,%3}, {%4,%5,%6,%7}, {%8,%9}, {%0,%1,%2,%3};"
        : "+f"(d[0]), "+f"(d[1]), "+f"(d[2]), "+f"(d[3])
        : "r"(a0), "r"(a1), "r"(a2), "r"(a3), "r"(b0), "r"(b1));
}
__device__ __forceinline__ void cp16(float* dst, const float* src) {
    unsigned saddr = (unsigned)__cvta_generic_to_shared(dst);
    asm volatile("cp.async.cg.shared.global [%0], [%1], 16;" :: "r"(saddr), "l"(src));
}

__global__ void __launch_bounds__(NT, 1)
tracker_fused_kernel(Params p) {
    extern __shared__ float smem[];
    float*    x_s     = smem + XS_OFF;
    uint32_t* x_u     = (uint32_t*)x_s;
    float*    wbuf    = smem + WB_OFF;
    uint32_t* wbuf_u  = (uint32_t*)wbuf;
    float*    gates_s = smem + GS_OFF;
    float*    h_sf    = smem + HS_OFF;
    uint32_t* h_u     = (uint32_t*)h_sf;
    float*    hwarp   = smem + HS_OFF;      // phase-A overlay
    float*    hid_s   = smem + HID_OFF;
    float*    fin_s   = smem + FIN_OFF;

    const int tid  = threadIdx.x;
    const int lane = tid & 31;
    const int w    = tid >> 5;        // 0..15
    const int gid  = lane >> 2;       // mma group id 0..7
    const int tig  = lane & 3;        // thread in group 0..3
    const int box0 = blockIdx.x * 32;

    // ============ Stage gates W (f-gate skipped), fp32, stride 100 ============
    #pragma unroll
    for (int it = 0; it < 18; it++) {
        int idx = tid + it * NT;
        int n = idx / 24, k4 = idx % 24;
        int row = (n < 128) ? n : n + 128;
        cp16(wbuf + n * 100 + 4 * k4, p.W_ih + row * 96 + 4 * k4);
    }
    asm volatile("cp.async.commit_group;");

    // ============ Phase A: boxes 2w, 2w+1 interleaved (writes tf32 to x_s) ============
    {
        const int b0 = 2 * w, b1 = 2 * w + 1;

        const float* wsaP = p.W_stats + lane * 6;
        const float* wsbP = p.W_stats + (lane + 32) * 6;
        float ws_a[6], ws_b[6];
        #pragma unroll
        for (int k = 0; k < 6; k++) { ws_a[k] = __ldg(wsaP + k); ws_b[k] = __ldg(wsbP + k); }
        float bs_a  = __ldg(p.b_stats + lane),  bs_b  = __ldg(p.b_stats + lane + 32);
        float gs_a  = __ldg(p.g_stats + lane),  gs_b  = __ldg(p.g_stats + lane + 32);
        float bes_a = __ldg(p.be_stats + lane), bes_b = __ldg(p.be_stats + lane + 32);
        float4 wb1v = __ldg((const float4*)(p.W_b1) + lane);
        float bb1 = __ldg(p.b_b1 + lane), gb1 = __ldg(p.g_b1 + lane), beb1 = __ldg(p.be_b1 + lane);
        float bb2 = __ldg(p.b_b2 + lane), gb2 = __ldg(p.g_b2 + lane), beb2 = __ldg(p.be_b2 + lane);

        float4 bxA = __ldg((const float4*)p.boxes + (box0 + b0));
        float4 bxB = __ldg((const float4*)p.boxes + (box0 + b1));
        float anA0 = fminf(fmaxf(bxA.x * (1.0f / 960.0f), 0.0f), 1.0f);
        float anA1 = fminf(fmaxf(bxA.y * (1.0f / 960.0f), 0.0f), 1.0f);
        float anA2 = fminf(fmaxf(bxA.z * (1.0f / 960.0f), 0.0f), 1.0f);
        float anA3 = fminf(fmaxf(bxA.w * (1.0f / 960.0f), 0.0f), 1.0f);
        float anB0 = fminf(fmaxf(bxB.x * (1.0f / 960.0f), 0.0f), 1.0f);
        float anB1 = fminf(fmaxf(bxB.y * (1.0f / 960.0f), 0.0f), 1.0f);
        float anB2 = fminf(fmaxf(bxB.z * (1.0f / 960.0f), 0.0f), 1.0f);
        float anB3 = fminf(fmaxf(bxB.w * (1.0f / 960.0f), 0.0f), 1.0f);

        int xA1 = min(max((int)floorf(anA0 * 60.0f), 0), GD - 1);
        int yA1 = min(max((int)floorf(anA1 * 60.0f), 0), GD - 1);
        int xA2 = min(max((int)ceilf(anA2 * 60.0f), xA1 + 1), GD);
        int yA2 = min(max((int)ceilf(anA3 * 60.0f), yA1 + 1), GD);
        int xB1 = min(max((int)floorf(anB0 * 60.0f), 0), GD - 1);
        int yB1 = min(max((int)floorf(anB1 * 60.0f), 0), GD - 1);
        int xB2 = min(max((int)ceilf(anB2 * 60.0f), xB1 + 1), GD);
        int yB2 = min(max((int)ceilf(anB3 * 60.0f), yB1 + 1), GD);
        int wdA = xA2 - xA1, areaA = wdA * (yA2 - yA1);
        int wdB = xB2 - xB1, areaB = wdB * (yB2 - yB1);
        int maxArea = max(areaA, areaB);

        float sA0 = 0.f, sA1 = 0.f, qA0 = 0.f, qA1 = 0.f;
        float mxA0 = -1e30f, mxA1 = -1e30f, mnA0 = 1e30f, mnA1 = 1e30f;
        float sB0 = 0.f, sB1 = 0.f, qB0 = 0.f, qB1 = 0.f;
        float mxB0 = -1e30f, mxB1 = -1e30f, mnB0 = 1e30f, mnB1 = 1e30f;

        for (int c = lane; c < maxArea; c += 32) {
            if (c < areaA) {
                int ry = c / wdA;
                int idx = (yA1 + ry) * GD + xA1 + (c - ry * wdA);
                float v0 = __ldg(p.mv + idx);
                float v1 = __ldg(p.mv + GG + idx);
                sA0 += v0; qA0 += v0 * v0; mxA0 = fmaxf(mxA0, v0); mnA0 = fminf(mnA0, v0);
                sA1 += v1; qA1 += v1 * v1; mxA1 = fmaxf(mxA1, v1); mnA1 = fminf(mnA1, v1);
            }
            if (c < areaB) {
                int ry = c / wdB;
                int idx = (yB1 + ry) * GD + xB1 + (c - ry * wdB);
                float v0 = __ldg(p.mv + idx);
                float v1 = __ldg(p.mv + GG + idx);
                sB0 += v0; qB0 += v0 * v0; mxB0 = fmaxf(mxB0, v0); mnB0 = fminf(mnB0, v0);
                sB1 += v1; qB1 += v1 * v1; mxB1 = fmaxf(mxB1, v1); mnB1 = fminf(mnB1, v1);
            }
        }
        #pragma unroll
        for (int o = 16; o; o >>= 1) {
            sA0 += __shfl_xor_sync(0xffffffffu, sA0, o);
            sA1 += __shfl_xor_sync(0xffffffffu, sA1, o);
            qA0 += __shfl_xor_sync(0xffffffffu, qA0, o);
            qA1 += __shfl_xor_sync(0xffffffffu, qA1, o);
            sB0 += __shfl_xor_sync(0xffffffffu, sB0, o);
            sB1 += __shfl_xor_sync(0xffffffffu, sB1, o);
            qB0 += __shfl_xor_sync(0xffffffffu, qB0, o);
            qB1 += __shfl_xor_sync(0xffffffffu, qB1, o);
            mxA0 = fmaxf(mxA0, __shfl_xor_sync(0xffffffffu, mxA0, o));
            mxA1 = fmaxf(mxA1, __shfl_xor_sync(0xffffffffu, mxA1, o));
            mnA0 = fminf(mnA0, __shfl_xor_sync(0xffffffffu, mnA0, o));
            mnA1 = fminf(mnA1, __shfl_xor_sync(0xffffffffu, mnA1, o));
            mxB0 = fmaxf(mxB0, __shfl_xor_sync(0xffffffffu, mxB0, o));
            mxB1 = fmaxf(mxB1, __shfl_xor_sync(0xffffffffu, mxB1, o));
            mnB0 = fminf(mnB0, __shfl_xor_sync(0xffffffffu, mnB0, o));
            mnB1 = fminf(mnB1, __shfl_xor_sync(0xffffffffu, mnB1, o));
        }
        float rcA = __fdividef(1.0f, (float)areaA);
        float rcB = __fdividef(1.0f, (float)areaB);
        float mA0 = sA0 * rcA, mA1 = sA1 * rcA;
        float mB0 = sB0 * rcB, mB1 = sB1 * rcB;
        float stA[6], stB[6];
        stA[0] = mA0; stA[1] = mA1;
        stA[2] = sqrtf(fmaxf(qA0 * rcA - mA0 * mA0, 0.0f));
        stA[3] = sqrtf(fmaxf(qA1 * rcA - mA1 * mA1, 0.0f));
        stA[4] = mxA0 - mnA0; stA[5] = mxA1 - mnA1;
        stB[0] = mB0; stB[1] = mB1;
        stB[2] = sqrtf(fmaxf(qB0 * rcB - mB0 * mB0, 0.0f));
        stB[3] = sqrtf(fmaxf(qB1 * rcB - mB1 * mB1, 0.0f));
        stB[4] = mxB0 - mnB0; stB[5] = mxB1 - mnB1;

        float zAa = bs_a, zAb = bs_b, zBa = bs_a, zBb = bs_b;
        #pragma unroll
        for (int k = 0; k < 6; k++) {
            zAa = fmaf(stA[k], ws_a[k], zAa);
            zAb = fmaf(stA[k], ws_b[k], zAb);
            zBa = fmaf(stB[k], ws_a[k], zBa);
            zBb = fmaf(stB[k], ws_b[k], zBb);
        }
        {
            float sA = zAa + zAb, qA = zAa * zAa + zAb * zAb;
            float sB = zBa + zBb, qB = zBa * zBa + zBb * zBb;
            #pragma unroll
            for (int o = 16; o; o >>= 1) {
                sA += __shfl_xor_sync(0xffffffffu, sA, o);
                qA += __shfl_xor_sync(0xffffffffu, qA, o);
                sB += __shfl_xor_sync(0xffffffffu, sB, o);
                qB += __shfl_xor_sync(0xffffffffu, qB, o);
            }
            float muA = sA * (1.0f / 64.0f);
            float invA = rsqrtf(fmaxf(qA * (1.0f / 64.0f) - muA * muA, 0.0f) + 1e-5f);
            float muB = sB * (1.0f / 64.0f);
            float invB = rsqrtf(fmaxf(qB * (1.0f / 64.0f) - muB * muB, 0.0f) + 1e-5f);
            x_u[b0 * 100 + lane]      = tf32cvt(fmaxf(fmaf((zAa - muA) * invA, gs_a, bes_a), 0.0f));
            x_u[b0 * 100 + 32 + lane] = tf32cvt(fmaxf(fmaf((zAb - muA) * invA, gs_b, bes_b), 0.0f));
            x_u[b1 * 100 + lane]      = tf32cvt(fmaxf(fmaf((zBa - muB) * invB, gs_a, bes_a), 0.0f));
            x_u[b1 * 100 + 32 + lane] = tf32cvt(fmaxf(fmaf((zBb - muB) * invB, gs_b, bes_b), 0.0f));
        }

        float tA = bb1, tB = bb1;
        tA = fmaf(anA0, wb1v.x, tA); tB = fmaf(anB0, wb1v.x, tB);
        tA = fmaf(anA1, wb1v.y, tA); tB = fmaf(anB1, wb1v.y, tB);
        tA = fmaf(anA2, wb1v.z, tA); tB = fmaf(anB2, wb1v.z, tB);
        tA = fmaf(anA3, wb1v.w, tA); tB = fmaf(anB3, wb1v.w, tB);
        {
            float sA = tA, qA = tA * tA, sB = tB, qB = tB * tB;
            #pragma unroll
            for (int o = 16; o; o >>= 1) {
                sA += __shfl_xor_sync(0xffffffffu, sA, o);
                qA += __shfl_xor_sync(0xffffffffu, qA, o);
                sB += __shfl_xor_sync(0xffffffffu, sB, o);
                qB += __shfl_xor_sync(0xffffffffu, qB, o);
            }
            float muA = sA * (1.0f / 32.0f);
            float invA = rsqrtf(fmaxf(qA * (1.0f / 32.0f) - muA * muA, 0.0f) + 1e-5f);
            float muB = sB * (1.0f / 32.0f);
            float invB = rsqrtf(fmaxf(qB * (1.0f / 32.0f) - muB * muB, 0.0f) + 1e-5f);
            hwarp[b0 * 32 + lane] = fmaxf(fmaf((tA - muA) * invA, gb1, beb1), 0.0f);
            hwarp[b1 * 32 + lane] = fmaxf(fmaf((tB - muB) * invB, gb1, beb1), 0.0f);
        }
        __syncwarp();
        float tA0 = bb2, tA1 = 0.0f, tB0 = bb2, tB1 = 0.0f;
        const float* wb2 = p.W_b2 + lane * 32;
        #pragma unroll
        for (int k4 = 0; k4 < 8; k4 += 2) {
            float4 wva = __ldg((const float4*)wb2 + k4);
            float4 wvb = __ldg((const float4*)wb2 + k4 + 1);
            const float* hpA = hwarp + b0 * 32 + 4 * k4;
            const float* hpB = hwarp + b1 * 32 + 4 * k4;
            tA0 = fmaf(hpA[0], wva.x, tA0); tB0 = fmaf(hpB[0], wva.x, tB0);
            tA0 = fmaf(hpA[1], wva.y, tA0); tB0 = fmaf(hpB[1], wva.y, tB0);
            tA0 = fmaf(hpA[2], wva.z, tA0); tB0 = fmaf(hpB[2], wva.z, tB0);
            tA0 = fmaf(hpA[3], wva.w, tA0); tB0 = fmaf(hpB[3], wva.w, tB0);
            tA1 = fmaf(hpA[4], wvb.x, tA1); tB1 = fmaf(hpB[4], wvb.x, tB1);
            tA1 = fmaf(hpA[5], wvb.y, tA1); tB1 = fmaf(hpB[5], wvb.y, tB1);
            tA1 = fmaf(hpA[6], wvb.z, tA1); tB1 = fmaf(hpB[6], wvb.z, tB1);
            tA1 = fmaf(hpA[7], wvb.w, tA1); tB1 = fmaf(hpB[7], wvb.w, tB1);
        }
        __syncwarp();
        {
            float t2A = tA0 + tA1, t2B = tB0 + tB1;
            float sA = t2A, qA = t2A * t2A, sB = t2B, qB = t2B * t2B;
            #pragma unroll
            for (int o = 16; o; o >>= 1) {
                sA += __shfl_xor_sync(0xffffffffu, sA, o);
                qA += __shfl_xor_sync(0xffffffffu, qA, o);
                sB += __shfl_xor_sync(0xffffffffu, sB, o);
                qB += __shfl_xor_sync(0xffffffffu, qB, o);
            }
            float muA = sA * (1.0f / 32.0f);
            float invA = rsqrtf(fmaxf(qA * (1.0f / 32.0f) - muA * muA, 0.0f) + 1e-5f);
            float muB = sB * (1.0f / 32.0f);
            float invB = rsqrtf(fmaxf(qB * (1.0f / 32.0f) - muB * muB, 0.0f) + 1e-5f);
            x_u[b0 * 100 + 64 + lane] = tf32cvt(fmaxf(fmaf((t2A - muA) * invA, gb2, beb2), 0.0f));
            x_u[b1 * 100 + 64 + lane] = tf32cvt(fmaxf(fmaf((t2B - muB) * invB, gb2, beb2), 0.0f));
        }
    }

    asm volatile("cp.async.wait_group 0;");
    __syncthreads();

    // ============ Convert gates W to tf32 in smem ============
    #pragma unroll
    for (int it = 0; it < 19; it++) {
        int idx = tid + it * NT;
        if (idx < 9600) {
            float4 v = *(float4*)(wbuf + 4 * idx);
            uint4 r;
            r.x = tf32cvt(v.x); r.y = tf32cvt(v.y);
            r.z = tf32cvt(v.z); r.w = tf32cvt(v.w);
            *(uint4*)(wbuf_u + 4 * idx) = r;
        }
    }
    __syncthreads();

    // ============ Gates GEMM via tf32 mma: D[32x384] ============
    // warp: mt = w&1 (M-tile of 16 boxes), ng = w>>1 (48 cols)
    const int mt = w & 1;
    const int ng = w >> 1;
    const int m0 = mt * 16;

    float dacc[6][4];
    #pragma unroll
    for (int j = 0; j < 6; j++)
        #pragma unroll
        for (int q = 0; q < 4; q++) dacc[j][q] = 0.0f;

    #pragma unroll
    for (int ks = 0; ks < 12; ks++) {
        int k0 = 8 * ks;
        uint32_t a0 = x_u[(m0 + gid) * 100 + k0 + tig];
        uint32_t a1 = x_u[(m0 + gid + 8) * 100 + k0 + tig];
        uint32_t a2 = x_u[(m0 + gid) * 100 + k0 + tig + 4];
        uint32_t a3 = x_u[(m0 + gid + 8) * 100 + k0 + tig + 4];
        #pragma unroll
        for (int j = 0; j < 6; j++) {
            int n = ng * 48 + 8 * j + gid;
            uint32_t b0 = wbuf_u[n * 100 + k0 + tig];
            uint32_t b1 = wbuf_u[n * 100 + k0 + tig + 4];
            mma_tf32(dacc[j], a0, a1, a2, a3, b0, b1);
        }
    }
    __syncthreads();   // all gates-W reads done (gates_s overlays o-gate rows)

    // ---- write D to gates_s [32][388] ----
    #pragma unroll
    for (int j = 0; j < 6; j++) {
        int nc = ng * 48 + 8 * j + 2 * tig;
        *(float2*)(gates_s + (m0 + gid) * 388 + nc)     = make_float2(dacc[j][0], dacc[j][1]);
        *(float2*)(gates_s + (m0 + gid + 8) * 388 + nc) = make_float2(dacc[j][2], dacc[j][3]);
    }

    // ---- stage heads weights into wbuf[0,25344) (stride 132), overlaps LSTM ----
    #pragma unroll
    for (int it = 0; it < 12; it++) {
        int idx = tid + it * NT;
        int n = idx >> 5, k4 = idx & 31;
        const float* src = (n < 64) ? (p.W_p1 + n * 128)
                         : (n < 128) ? (p.W_s1 + (n - 64) * 128)
                                     : (p.W_c1 + (n - 128) * 128);
        cp16(wbuf + n * 132 + 4 * k4, src + 4 * k4);
    }
    asm volatile("cp.async.commit_group;");
    __syncthreads();   // D visible to all

    // ============ LSTM elementwise (h0=c0=0), writes tf32 h ============
    {
        int hu = tid & 127;
        float bi  = __ldg(p.b_ih + hu)       + __ldg(p.b_hh + hu);
        float bgv = __ldg(p.b_ih + 256 + hu) + __ldg(p.b_hh + 256 + hu);
        float bo  = __ldg(p.b_ih + 384 + hu) + __ldg(p.b_hh + 384 + hu);
        int bbase = tid >> 7;
        #pragma unroll
        for (int it = 0; it < 8; it++) {
            int b = bbase + 4 * it;
            float iv = gates_s[b * 388 + hu] + bi;
            float gv = gates_s[b * 388 + 128 + hu] + bgv;
            float ov = gates_s[b * 388 + 256 + hu] + bo;
            float c = sigfast(iv) * tanhfast(gv);
            h_u[b * 132 + hu] = tf32cvt(sigfast(ov) * tanhfast(c));
        }
    }

    asm volatile("cp.async.wait_group 0;");
    __syncthreads();

    // ============ Convert heads W to tf32 ============
    #pragma unroll
    for (int it = 0; it < 13; it++) {
        int idx = tid + it * NT;
        if (idx < 6336) {
            float4 v = *(float4*)(wbuf + 4 * idx);
            uint4 r;
            r.x = tf32cvt(v.x); r.y = tf32cvt(v.y);
            r.z = tf32cvt(v.z); r.w = tf32cvt(v.w);
            *(uint4*)(wbuf_u + 4 * idx) = r;
        }
    }
    __syncthreads();

    // ============ Heads GEMM via tf32 mma: D2[32x192] ============
    float hacc[3][4];
    #pragma unroll
    for (int j = 0; j < 3; j++)
        #pragma unroll
        for (int q = 0; q < 4; q++) hacc[j][q] = 0.0f;

    #pragma unroll
    for (int ks = 0; ks < 16; ks++) {
        int k0 = 8 * ks;
        uint32_t a0 = h_u[(m0 + gid) * 132 + k0 + tig];
        uint32_t a1 = h_u[(m0 + gid + 8) * 132 + k0 + tig];
        uint32_t a2 = h_u[(m0 + gid) * 132 + k0 + tig + 4];
        uint32_t a3 = h_u[(m0 + gid + 8) * 132 + k0 + tig + 4];
        #pragma unroll
        for (int j = 0; j < 3; j++) {
            int n = ng * 24 + 8 * j + gid;
            uint32_t b0 = wbuf_u[n * 132 + k0 + tig];
            uint32_t b1 = wbuf_u[n * 132 + k0 + tig + 4];
            mma_tf32(hacc[j], a0, a1, a2, a3, b0, b1);
        }
    }

    // ---- epilogue: bias + relu -> hid_s [32][196] ----
    #pragma unroll
    for (int j = 0; j < 3; j++) {
        int nc = ng * 24 + 8 * j + 2 * tig;
        float bias0 = (nc < 64) ? __ldg(p.b_p1 + nc)
                    : (nc < 128) ? __ldg(p.b_s1 + nc - 64)
                                 : __ldg(p.b_c1 + nc - 128);
        int nc1 = nc + 1;
        float bias1 = (nc1 < 64) ? __ldg(p.b_p1 + nc1)
                    : (nc1 < 128) ? __ldg(p.b_s1 + nc1 - 64)
                                  : __ldg(p.b_c1 + nc1 - 128);
        *(float2*)(hid_s + (m0 + gid) * 196 + nc) =
            make_float2(fmaxf(hacc[j][0] + bias0, 0.0f), fmaxf(hacc[j][1] + bias1, 0.0f));
        *(float2*)(hid_s + (m0 + gid + 8) * 196 + nc) =
            make_float2(fmaxf(hacc[j][2] + bias0, 0.0f), fmaxf(hacc[j][3] + bias1, 0.0f));
    }
    __syncthreads();

    // ============ Head second layers (5 scalars per box) ============
    if (tid < 160) {
        int b = tid / 5, o = tid % 5;
        const float* hp = hid_s + b * 196 + ((o < 2) ? 0 : (o < 4) ? 64 : 128);
        const float* wp;
        float a;
        if (o == 0)      { wp = p.W_p2;      a = __ldg(p.b_p2); }
        else if (o == 1) { wp = p.W_p2 + 64; a = __ldg(p.b_p2 + 1); }
        else if (o == 2) { wp = p.W_s2;      a = __ldg(p.b_s2); }
        else if (o == 3) { wp = p.W_s2 + 64; a = __ldg(p.b_s2 + 1); }
        else             { wp = p.W_c2;      a = __ldg(p.b_c2); }
        #pragma unroll
        for (int k4 = 0; k4 < 16; k4++) {
            float4 hv = *(const float4*)(hp + 4 * k4);
            float4 wv = __ldg((const float4*)wp + k4);
            a = fmaf(hv.x, wv.x, a);
            a = fmaf(hv.y, wv.y, a);
            a = fmaf(hv.z, wv.z, a);
            a = fmaf(hv.w, wv.w, a);
        }
        fin_s[b * 5 + o] = a;
    }
    __syncthreads();

    // ============ Decode + output ============
    if (tid < 32) {
        int b = tid;
        float4 bx = __ldg((const float4*)p.boxes + (box0 + b));
        float cx = (bx.x + bx.z) * 0.5f, cy = (bx.y + bx.w) * 0.5f;
        float wd = bx.z - bx.x, hg = bx.w - bx.y;
        float ncx = cx + fin_s[b * 5 + 0];
        float ncy = cy + fin_s[b * 5 + 1];
        float nw = wd * __expf(fin_s[b * 5 + 2]);
        float nh = hg * __expf(fin_s[b * 5 + 3]);
        float conf = __fdividef(1.0f, 1.0f + __expf(-fin_s[b * 5 + 4]));
        float* op = p.out + (box0 + b) * 5;
        op[0] = ncx - nw * 0.5f;
        op[1] = ncy - nh * 0.5f;
        op[2] = ncx + nw * 0.5f;
        op[3] = ncy + nh * 0.5f;
        op[4] = conf;
    }
}

extern "C" void kernel_launch(void* const* d_in, const int* in_sizes, int n_in,
                              void* d_out, int out_size) {
    (void)in_sizes; (void)n_in; (void)out_size;
    Params p;
    p.mv       = (const float*)d_in[0];
    p.boxes    = (const float*)d_in[1];
    p.W_stats  = (const float*)d_in[2];
    p.b_stats  = (const float*)d_in[3];
    p.g_stats  = (const float*)d_in[4];
    p.be_stats = (const float*)d_in[5];
    p.W_b1     = (const float*)d_in[6];
    p.b_b1     = (const float*)d_in[7];
    p.g_b1     = (const float*)d_in[8];
    p.be_b1    = (const float*)d_in[9];
    p.W_b2     = (const float*)d_in[10];
    p.b_b2     = (const float*)d_in[11];
    p.g_b2     = (const float*)d_in[12];
    p.be_b2    = (const float*)d_in[13];
    p.W_ih     = (const float*)d_in[14];
    p.W_hh     = (const float*)d_in[15];
    p.b_ih     = (const float*)d_in[16];
    p.b_hh     = (const float*)d_in[17];
    p.W_p1     = (const float*)d_in[18];
    p.b_p1     = (const float*)d_in[19];
    p.W_p2     = (const float*)d_in[20];
    p.b_p2     = (const float*)d_in[21];
    p.W_s1     = (const float*)d_in[22];
    p.b_s1     = (const float*)d_in[23];
    p.W_s2     = (const float*)d_in[24];
    p.b_s2     = (const float*)d_in[25];
    p.W_c1     = (const float*)d_in[26];
    p.b_c1     = (const float*)d_in[27];
    p.W_c2     = (const float*)d_in[28];
    p.b_c2     = (const float*)d_in[29];
    p.out      = (float*)d_out;

    cudaFuncSetAttribute(tracker_fused_kernel,
                         cudaFuncAttributeMaxDynamicSharedMemorySize, SMEM_BYTES);
    tracker_fused_kernel<<<128, NT, SMEM_BYTES>>>(p);
}

// round 10
// speedup vs baseline: 1.5814x; 1.1081x over previous
#include <cuda_runtime.h>
#include <math.h>
#include <stdint.h>

#define GD 60
#define GG 3600
#define NT 512

// device scratch: pre-converted tf32 weights (packed) + combined biases
__device__ uint32_t g_Wg[384 * 96];    // gates W, packed cols, k-pair-permuted
__device__ uint32_t g_Wh[192 * 128];   // heads W, k-pair-permuted
__device__ float    g_bias[384];       // [i(128) | g(128) | o(128)] = b_ih + b_hh

// shared memory layout (floats):
//   x_s  @ 0     : 32*104 = 3328   (tf32 bits, k-permuted)
//   wbuf @ 3328  : 384*104 = 39936 (gates W tf32; heads W 192*136=26112 fits)
//   h_s  @ 43264 : 32*136 = 4352   (tf32 bits, k-permuted; phase-A hwarp overlays)
//   hid  @ 47616 : 32*196 = 6272
//   fin  @ 53888 : 160
#define XS_OFF   0
#define WB_OFF   3328
#define HS_OFF   43264
#define HID_OFF  47616
#define FIN_OFF  53888
#define SMEM_FLOATS 54048
#define SMEM_BYTES (SMEM_FLOATS * 4)

struct Params {
    const float* mv;
    const float* boxes;
    const float* W_stats; const float* b_stats; const float* g_stats; const float* be_stats;
    const float* W_b1;    const float* b_b1;    const float* g_b1;    const float* be_b1;
    const float* W_b2;    const float* b_b2;    const float* g_b2;    const float* be_b2;
    const float* W_ih;    const float* W_hh;    const float* b_ih;    const float* b_hh;
    const float* W_p1;    const float* b_p1;    const float* W_p2;    const float* b_p2;
    const float* W_s1;    const float* b_s1;    const float* W_s2;    const float* b_s2;
    const float* W_c1;    const float* b_c1;    const float* W_c2;    const float* b_c2;
    float* out;
};

__device__ __forceinline__ float tanhfast(float x) {
    float y;
    asm("tanh.approx.f32 %0, %1;" : "=f"(y) : "f"(x));
    return y;
}
__device__ __forceinline__ float sigfast(float x) {
    return fmaf(0.5f, tanhfast(0.5f * x), 0.5f);
}
__device__ __forceinline__ uint32_t tf32cvt(float x) {
    uint32_t r;
    asm("cvt.rna.tf32.f32 %0, %1;" : "=r"(r) : "f"(x));
    return r;
}
// within each 8-k block: k<4 -> 2k ; k>=4 -> 2(k-4)+1   (pairs (k,k+4) adjacent)
__device__ __forceinline__ int permk(int c) {
    return (c & ~7) | ((c & 3) << 1) | ((c & 4) >> 2);
}
__device__ __forceinline__ void mma_tf32(float* d,
                                         uint32_t a0, uint32_t a1, uint32_t a2, uint32_t a3,
                                         uint32_t b0, uint32_t b1) {
    asm volatile(
        "mma.sync.aligned.m16n8k8.row.col.f32.tf32.tf32.f32 "
        "{%0,%1,%2,%3}, {%4,%5,%6,%7}, {%8,%9}, {%0,%1,%2,%3};"
        : "+f"(d[0]), "+f"(d[1]), "+f"(d[2]), "+f"(d[3])
        : "r"(a0), "r"(a1), "r"(a2), "r"(a3), "r"(b0), "r"(b1));
}
__device__ __forceinline__ void cp16(void* dst, const void* src) {
    unsigned saddr = (unsigned)__cvta_generic_to_shared(dst);
    asm volatile("cp.async.cg.shared.global [%0], [%1], 16;" :: "r"(saddr), "l"(src));
}

// ===========================================================================
// Prep kernel: convert + pack weights to tf32 once per launch.
// Gates packed col c: ng=c/48, cl=c%48, j=cl/8, r=cl%8 -> gate=j%3,
// u = 16ng + 8*(j/3) + r. Original W_ih row: i=u, g=256+u, o=384+u (f skipped).
// ===========================================================================
__global__ void __launch_bounds__(256)
prep_kernel(Params p) {
    int tid = blockIdx.x * blockDim.x + threadIdx.x;
    int stride = gridDim.x * blockDim.x;
    for (int idx = tid; idx < 384 * 96; idx += stride) {
        int c = idx / 96, k = idx % 96;
        int ng = c / 48, cl = c % 48;
        int j = cl >> 3, r = cl & 7;
        int gate = j % 3;
        int u = 16 * ng + 8 * (j / 3) + r;
        int row = (gate == 0) ? u : (gate == 1) ? 256 + u : 384 + u;
        g_Wg[c * 96 + permk(k)] = tf32cvt(__ldg(p.W_ih + row * 96 + k));
    }
    for (int idx = tid; idx < 192 * 128; idx += stride) {
        int n = idx >> 7, k = idx & 127;
        const float* src = (n < 64) ? (p.W_p1 + n * 128)
                         : (n < 128) ? (p.W_s1 + (n - 64) * 128)
                                     : (p.W_c1 + (n - 128) * 128);
        g_Wh[n * 128 + permk(k)] = tf32cvt(__ldg(src + k));
    }
    if (tid < 384) {
        int t = tid >> 7, u = tid & 127;
        int row = (t == 0) ? u : (t == 1) ? 256 + u : 384 + u;
        g_bias[tid] = __ldg(p.b_ih + row) + __ldg(p.b_hh + row);
    }
}

// ===========================================================================
// Main fused kernel
// ===========================================================================
__global__ void __launch_bounds__(NT, 1)
tracker_fused_kernel(Params p) {
    extern __shared__ float smem[];
    uint32_t* x_u    = (uint32_t*)(smem + XS_OFF);
    float*    wbuf   = smem + WB_OFF;
    uint32_t* wbuf_u = (uint32_t*)wbuf;
    uint32_t* h_u    = (uint32_t*)(smem + HS_OFF);
    float*    hwarp  = smem + HS_OFF;      // phase-A overlay (1024 floats)
    float*    hid_s  = smem + HID_OFF;
    float*    fin_s  = smem + FIN_OFF;

    const int tid  = threadIdx.x;
    const int lane = tid & 31;
    const int w    = tid >> 5;        // 0..15
    const int gid  = lane >> 2;       // 0..7
    const int tig  = lane & 3;        // 0..3
    const int box0 = blockIdx.x * 32;

    // ---- stage gates W (already tf32 + packed): 9216 float4 ----
    #pragma unroll
    for (int it = 0; it < 18; it++) {
        int idx = tid + it * NT;
        int n = idx / 24, k4 = idx % 24;
        cp16(wbuf_u + n * 104 + 4 * k4, g_Wg + n * 96 + 4 * k4);
    }
    asm volatile("cp.async.commit_group;");

    // ============ Phase A: boxes 2w, 2w+1 interleaved -> x_u (tf32, permuted) ============
    {
        const int b0 = 2 * w, b1 = 2 * w + 1;

        const float* wsaP = p.W_stats + lane * 6;
        const float* wsbP = p.W_stats + (lane + 32) * 6;
        float ws_a[6], ws_b[6];
        #pragma unroll
        for (int k = 0; k < 6; k++) { ws_a[k] = __ldg(wsaP + k); ws_b[k] = __ldg(wsbP + k); }
        float bs_a  = __ldg(p.b_stats + lane),  bs_b  = __ldg(p.b_stats + lane + 32);
        float gs_a  = __ldg(p.g_stats + lane),  gs_b  = __ldg(p.g_stats + lane + 32);
        float bes_a = __ldg(p.be_stats + lane), bes_b = __ldg(p.be_stats + lane + 32);
        float4 wb1v = __ldg((const float4*)(p.W_b1) + lane);
        float bb1 = __ldg(p.b_b1 + lane), gb1 = __ldg(p.g_b1 + lane), beb1 = __ldg(p.be_b1 + lane);
        float bb2 = __ldg(p.b_b2 + lane), gb2 = __ldg(p.g_b2 + lane), beb2 = __ldg(p.be_b2 + lane);

        float4 bxA = __ldg((const float4*)p.boxes + (box0 + b0));
        float4 bxB = __ldg((const float4*)p.boxes + (box0 + b1));
        float anA0 = fminf(fmaxf(bxA.x * (1.0f / 960.0f), 0.0f), 1.0f);
        float anA1 = fminf(fmaxf(bxA.y * (1.0f / 960.0f), 0.0f), 1.0f);
        float anA2 = fminf(fmaxf(bxA.z * (1.0f / 960.0f), 0.0f), 1.0f);
        float anA3 = fminf(fmaxf(bxA.w * (1.0f / 960.0f), 0.0f), 1.0f);
        float anB0 = fminf(fmaxf(bxB.x * (1.0f / 960.0f), 0.0f), 1.0f);
        float anB1 = fminf(fmaxf(bxB.y * (1.0f / 960.0f), 0.0f), 1.0f);
        float anB2 = fminf(fmaxf(bxB.z * (1.0f / 960.0f), 0.0f), 1.0f);
        float anB3 = fminf(fmaxf(bxB.w * (1.0f / 960.0f), 0.0f), 1.0f);

        int xA1 = min(max((int)floorf(anA0 * 60.0f), 0), GD - 1);
        int yA1 = min(max((int)floorf(anA1 * 60.0f), 0), GD - 1);
        int xA2 = min(max((int)ceilf(anA2 * 60.0f), xA1 + 1), GD);
        int yA2 = min(max((int)ceilf(anA3 * 60.0f), yA1 + 1), GD);
        int xB1 = min(max((int)floorf(anB0 * 60.0f), 0), GD - 1);
        int yB1 = min(max((int)floorf(anB1 * 60.0f), 0), GD - 1);
        int xB2 = min(max((int)ceilf(anB2 * 60.0f), xB1 + 1), GD);
        int yB2 = min(max((int)ceilf(anB3 * 60.0f), yB1 + 1), GD);
        int wdA = xA2 - xA1, areaA = wdA * (yA2 - yA1);
        int wdB = xB2 - xB1, areaB = wdB * (yB2 - yB1);
        int maxArea = max(areaA, areaB);

        float sA0 = 0.f, sA1 = 0.f, qA0 = 0.f, qA1 = 0.f;
        float mxA0 = -1e30f, mxA1 = -1e30f, mnA0 = 1e30f, mnA1 = 1e30f;
        float sB0 = 0.f, sB1 = 0.f, qB0 = 0.f, qB1 = 0.f;
        float mxB0 = -1e30f, mxB1 = -1e30f, mnB0 = 1e30f, mnB1 = 1e30f;

        for (int c = lane; c < maxArea; c += 32) {
            if (c < areaA) {
                int ry = c / wdA;
                int idx = (yA1 + ry) * GD + xA1 + (c - ry * wdA);
                float v0 = __ldg(p.mv + idx);
                float v1 = __ldg(p.mv + GG + idx);
                sA0 += v0; qA0 += v0 * v0; mxA0 = fmaxf(mxA0, v0); mnA0 = fminf(mnA0, v0);
                sA1 += v1; qA1 += v1 * v1; mxA1 = fmaxf(mxA1, v1); mnA1 = fminf(mnA1, v1);
            }
            if (c < areaB) {
                int ry = c / wdB;
                int idx = (yB1 + ry) * GD + xB1 + (c - ry * wdB);
                float v0 = __ldg(p.mv + idx);
                float v1 = __ldg(p.mv + GG + idx);
                sB0 += v0; qB0 += v0 * v0; mxB0 = fmaxf(mxB0, v0); mnB0 = fminf(mnB0, v0);
                sB1 += v1; qB1 += v1 * v1; mxB1 = fmaxf(mxB1, v1); mnB1 = fminf(mnB1, v1);
            }
        }
        #pragma unroll
        for (int o = 16; o; o >>= 1) {
            sA0 += __shfl_xor_sync(0xffffffffu, sA0, o);
            sA1 += __shfl_xor_sync(0xffffffffu, sA1, o);
            qA0 += __shfl_xor_sync(0xffffffffu, qA0, o);
            qA1 += __shfl_xor_sync(0xffffffffu, qA1, o);
            sB0 += __shfl_xor_sync(0xffffffffu, sB0, o);
            sB1 += __shfl_xor_sync(0xffffffffu, sB1, o);
            qB0 += __shfl_xor_sync(0xffffffffu, qB0, o);
            qB1 += __shfl_xor_sync(0xffffffffu, qB1, o);
            mxA0 = fmaxf(mxA0, __shfl_xor_sync(0xffffffffu, mxA0, o));
            mxA1 = fmaxf(mxA1, __shfl_xor_sync(0xffffffffu, mxA1, o));
            mnA0 = fminf(mnA0, __shfl_xor_sync(0xffffffffu, mnA0, o));
            mnA1 = fminf(mnA1, __shfl_xor_sync(0xffffffffu, mnA1, o));
            mxB0 = fmaxf(mxB0, __shfl_xor_sync(0xffffffffu, mxB0, o));
            mxB1 = fmaxf(mxB1, __shfl_xor_sync(0xffffffffu, mxB1, o));
            mnB0 = fminf(mnB0, __shfl_xor_sync(0xffffffffu, mnB0, o));
            mnB1 = fminf(mnB1, __shfl_xor_sync(0xffffffffu, mnB1, o));
        }
        float rcA = __fdividef(1.0f, (float)areaA);
        float rcB = __fdividef(1.0f, (float)areaB);
        float mA0 = sA0 * rcA, mA1 = sA1 * rcA;
        float mB0 = sB0 * rcB, mB1 = sB1 * rcB;
        float stA[6], stB[6];
        stA[0] = mA0; stA[1] = mA1;
        stA[2] = sqrtf(fmaxf(qA0 * rcA - mA0 * mA0, 0.0f));
        stA[3] = sqrtf(fmaxf(qA1 * rcA - mA1 * mA1, 0.0f));
        stA[4] = mxA0 - mnA0; stA[5] = mxA1 - mnA1;
        stB[0] = mB0; stB[1] = mB1;
        stB[2] = sqrtf(fmaxf(qB0 * rcB - mB0 * mB0, 0.0f));
        stB[3] = sqrtf(fmaxf(qB1 * rcB - mB1 * mB1, 0.0f));
        stB[4] = mxB0 - mnB0; stB[5] = mxB1 - mnB1;

        float zAa = bs_a, zAb = bs_b, zBa = bs_a, zBb = bs_b;
        #pragma unroll
        for (int k = 0; k < 6; k++) {
            zAa = fmaf(stA[k], ws_a[k], zAa);
            zAb = fmaf(stA[k], ws_b[k], zAb);
            zBa = fmaf(stB[k], ws_a[k], zBa);
            zBb = fmaf(stB[k], ws_b[k], zBb);
        }
        {
            float sA = zAa + zAb, qA = zAa * zAa + zAb * zAb;
            float sB = zBa + zBb, qB = zBa * zBa + zBb * zBb;
            #pragma unroll
            for (int o = 16; o; o >>= 1) {
                sA += __shfl_xor_sync(0xffffffffu, sA, o);
                qA += __shfl_xor_sync(0xffffffffu, qA, o);
                sB += __shfl_xor_sync(0xffffffffu, sB, o);
                qB += __shfl_xor_sync(0xffffffffu, qB, o);
            }
            float muA = sA * (1.0f / 64.0f);
            float invA = rsqrtf(fmaxf(qA * (1.0f / 64.0f) - muA * muA, 0.0f) + 1e-5f);
            float muB = sB * (1.0f / 64.0f);
            float invB = rsqrtf(fmaxf(qB * (1.0f / 64.0f) - muB * muB, 0.0f) + 1e-5f);
            x_u[b0 * 104 + permk(lane)]      = tf32cvt(fmaxf(fmaf((zAa - muA) * invA, gs_a, bes_a), 0.0f));
            x_u[b0 * 104 + permk(lane + 32)] = tf32cvt(fmaxf(fmaf((zAb - muA) * invA, gs_b, bes_b), 0.0f));
            x_u[b1 * 104 + permk(lane)]      = tf32cvt(fmaxf(fmaf((zBa - muB) * invB, gs_a, bes_a), 0.0f));
            x_u[b1 * 104 + permk(lane + 32)] = tf32cvt(fmaxf(fmaf((zBb - muB) * invB, gs_b, bes_b), 0.0f));
        }

        float tA = bb1, tB = bb1;
        tA = fmaf(anA0, wb1v.x, tA); tB = fmaf(anB0, wb1v.x, tB);
        tA = fmaf(anA1, wb1v.y, tA); tB = fmaf(anB1, wb1v.y, tB);
        tA = fmaf(anA2, wb1v.z, tA); tB = fmaf(anB2, wb1v.z, tB);
        tA = fmaf(anA3, wb1v.w, tA); tB = fmaf(anB3, wb1v.w, tB);
        {
            float sA = tA, qA = tA * tA, sB = tB, qB = tB * tB;
            #pragma unroll
            for (int o = 16; o; o >>= 1) {
                sA += __shfl_xor_sync(0xffffffffu, sA, o);
                qA += __shfl_xor_sync(0xffffffffu, qA, o);
                sB += __shfl_xor_sync(0xffffffffu, sB, o);
                qB += __shfl_xor_sync(0xffffffffu, qB, o);
            }
            float muA = sA * (1.0f / 32.0f);
            float invA = rsqrtf(fmaxf(qA * (1.0f / 32.0f) - muA * muA, 0.0f) + 1e-5f);
            float muB = sB * (1.0f / 32.0f);
            float invB = rsqrtf(fmaxf(qB * (1.0f / 32.0f) - muB * muB, 0.0f) + 1e-5f);
            hwarp[b0 * 32 + lane] = fmaxf(fmaf((tA - muA) * invA, gb1, beb1), 0.0f);
            hwarp[b1 * 32 + lane] = fmaxf(fmaf((tB - muB) * invB, gb1, beb1), 0.0f);
        }
        __syncwarp();
        float tA0 = bb2, tA1 = 0.0f, tB0 = bb2, tB1 = 0.0f;
        const float* wb2 = p.W_b2 + lane * 32;
        #pragma unroll
        for (int k4 = 0; k4 < 8; k4 += 2) {
            float4 wva = __ldg((const float4*)wb2 + k4);
            float4 wvb = __ldg((const float4*)wb2 + k4 + 1);
            const float* hpA = hwarp + b0 * 32 + 4 * k4;
            const float* hpB = hwarp + b1 * 32 + 4 * k4;
            tA0 = fmaf(hpA[0], wva.x, tA0); tB0 = fmaf(hpB[0], wva.x, tB0);
            tA0 = fmaf(hpA[1], wva.y, tA0); tB0 = fmaf(hpB[1], wva.y, tB0);
            tA0 = fmaf(hpA[2], wva.z, tA0); tB0 = fmaf(hpB[2], wva.z, tB0);
            tA0 = fmaf(hpA[3], wva.w, tA0); tB0 = fmaf(hpB[3], wva.w, tB0);
            tA1 = fmaf(hpA[4], wvb.x, tA1); tB1 = fmaf(hpB[4], wvb.x, tB1);
            tA1 = fmaf(hpA[5], wvb.y, tA1); tB1 = fmaf(hpB[5], wvb.y, tB1);
            tA1 = fmaf(hpA[6], wvb.z, tA1); tB1 = fmaf(hpB[6], wvb.z, tB1);
            tA1 = fmaf(hpA[7], wvb.w, tA1); tB1 = fmaf(hpB[7], wvb.w, tB1);
        }
        __syncwarp();
        {
            float t2A = tA0 + tA1, t2B = tB0 + tB1;
            float sA = t2A, qA = t2A * t2A, sB = t2B, qB = t2B * t2B;
            #pragma unroll
            for (int o = 16; o; o >>= 1) {
                sA += __shfl_xor_sync(0xffffffffu, sA, o);
                qA += __shfl_xor_sync(0xffffffffu, qA, o);
                sB += __shfl_xor_sync(0xffffffffu, sB, o);
                qB += __shfl_xor_sync(0xffffffffu, qB, o);
            }
            float muA = sA * (1.0f / 32.0f);
            float invA = rsqrtf(fmaxf(qA * (1.0f / 32.0f) - muA * muA, 0.0f) + 1e-5f);
            float muB = sB * (1.0f / 32.0f);
            float invB = rsqrtf(fmaxf(qB * (1.0f / 32.0f) - muB * muB, 0.0f) + 1e-5f);
            x_u[b0 * 104 + permk(64 + lane)] = tf32cvt(fmaxf(fmaf((t2A - muA) * invA, gb2, beb2), 0.0f));
            x_u[b1 * 104 + permk(64 + lane)] = tf32cvt(fmaxf(fmaf((t2B - muB) * invB, gb2, beb2), 0.0f));
        }
    }

    asm volatile("cp.async.wait_group 0;");
    __syncthreads();   // x_u complete + gates W staged

    // ============ Gates GEMM via tf32 mma (LDS.64 fragments) ============
    const int mt = w & 1;         // M-tile (16 boxes)
    const int ng = w >> 1;        // 48 packed cols = 16 hidden units x (i,g,o)
    const int m0 = mt * 16;

    float dacc[6][4];
    #pragma unroll
    for (int j = 0; j < 6; j++)
        #pragma unroll
        for (int q = 0; q < 4; q++) dacc[j][q] = 0.0f;

    #pragma unroll
    for (int ks = 0; ks < 12; ks++) {
        int k0 = 8 * ks;
        uint2 aA = *(const uint2*)(x_u + (m0 + gid) * 104 + k0 + 2 * tig);      // (a0,a2)
        uint2 aB = *(const uint2*)(x_u + (m0 + gid + 8) * 104 + k0 + 2 * tig);  // (a1,a3)
        #pragma unroll
        for (int j = 0; j < 6; j++) {
            int n = ng * 48 + 8 * j + gid;
            uint2 bv = *(const uint2*)(wbuf_u + n * 104 + k0 + 2 * tig);        // (b0,b1)
            mma_tf32(dacc[j], aA.x, aB.x, aA.y, aB.y, bv.x, bv.y);
        }
    }
    __syncthreads();   // gates-W reads done -> wbuf reusable

    // ---- stage heads W (tf32, permuted): 6144 float4 ----
    #pragma unroll
    for (int it = 0; it < 12; it++) {
        int idx = tid + it * NT;
        int n = idx >> 5, k4 = idx & 31;
        cp16(wbuf_u + n * 136 + 4 * k4, g_Wh + n * 128 + 4 * k4);
    }
    asm volatile("cp.async.commit_group;");

    // ============ LSTM fully in registers -> h_u (tf32, permuted) ============
    // Thread's packed cols decode: j=3jj+gate, col r = 2tig+e -> u = 16ng+8jj+2tig+e
    #pragma unroll
    for (int jj = 0; jj < 2; jj++) {
        #pragma unroll
        for (int e = 0; e < 2; e++) {
            int u = 16 * ng + 8 * jj + 2 * tig + e;
            float bi = __ldg(g_bias + u);
            float bg = __ldg(g_bias + 128 + u);
            float bo = __ldg(g_bias + 256 + u);
            // row m0+gid
            {
                float iv = dacc[3 * jj + 0][e] + bi;
                float gv = dacc[3 * jj + 1][e] + bg;
                float ov = dacc[3 * jj + 2][e] + bo;
                float c = sigfast(iv) * tanhfast(gv);
                h_u[(m0 + gid) * 136 + permk(u)] = tf32cvt(sigfast(ov) * tanhfast(c));
            }
            // row m0+gid+8
            {
                float iv = dacc[3 * jj + 0][2 + e] + bi;
                float gv = dacc[3 * jj + 1][2 + e] + bg;
                float ov = dacc[3 * jj + 2][2 + e] + bo;
                float c = sigfast(iv) * tanhfast(gv);
                h_u[(m0 + gid + 8) * 136 + permk(u)] = tf32cvt(sigfast(ov) * tanhfast(c));
            }
        }
    }

    asm volatile("cp.async.wait_group 0;");
    __syncthreads();   // h complete + heads W staged

    // ============ Heads GEMM via tf32 mma (LDS.64 fragments) ============
    float hacc[3][4];
    #pragma unroll
    for (int j = 0; j < 3; j++)
        #pragma unroll
        for (int q = 0; q < 4; q++) hacc[j][q] = 0.0f;

    #pragma unroll
    for (int ks = 0; ks < 16; ks++) {
        int k0 = 8 * ks;
        uint2 aA = *(const uint2*)(h_u + (m0 + gid) * 136 + k0 + 2 * tig);
        uint2 aB = *(const uint2*)(h_u + (m0 + gid + 8) * 136 + k0 + 2 * tig);
        #pragma unroll
        for (int j = 0; j < 3; j++) {
            int n = ng * 24 + 8 * j + gid;
            uint2 bv = *(const uint2*)(wbuf_u + n * 136 + k0 + 2 * tig);
            mma_tf32(hacc[j], aA.x, aB.x, aA.y, aB.y, bv.x, bv.y);
        }
    }

    // ---- epilogue: bias + relu -> hid_s [32][196] ----
    #pragma unroll
    for (int j = 0; j < 3; j++) {
        int nc = ng * 24 + 8 * j + 2 * tig;
        float bias0 = (nc < 64) ? __ldg(p.b_p1 + nc)
                    : (nc < 128) ? __ldg(p.b_s1 + nc - 64)
                                 : __ldg(p.b_c1 + nc - 128);
        int nc1 = nc + 1;
        float bias1 = (nc1 < 64) ? __ldg(p.b_p1 + nc1)
                    : (nc1 < 128) ? __ldg(p.b_s1 + nc1 - 64)
                                  : __ldg(p.b_c1 + nc1 - 128);
        *(float2*)(hid_s + (m0 + gid) * 196 + nc) =
            make_float2(fmaxf(hacc[j][0] + bias0, 0.0f), fmaxf(hacc[j][1] + bias1, 0.0f));
        *(float2*)(hid_s + (m0 + gid + 8) * 196 + nc) =
            make_float2(fmaxf(hacc[j][2] + bias0, 0.0f), fmaxf(hacc[j][3] + bias1, 0.0f));
    }
    __syncthreads();

    // ============ Head second layers (5 scalars per box) ============
    if (tid < 160) {
        int b = tid / 5, o = tid % 5;
        const float* hp = hid_s + b * 196 + ((o < 2) ? 0 : (o < 4) ? 64 : 128);
        const float* wp;
        float a;
        if (o == 0)      { wp = p.W_p2;      a = __ldg(p.b_p2); }
        else if (o == 1) { wp = p.W_p2 + 64; a = __ldg(p.b_p2 + 1); }
        else if (o == 2) { wp = p.W_s2;      a = __ldg(p.b_s2); }
        else if (o == 3) { wp = p.W_s2 + 64; a = __ldg(p.b_s2 + 1); }
        else             { wp = p.W_c2;      a = __ldg(p.b_c2); }
        #pragma unroll
        for (int k4 = 0; k4 < 16; k4++) {
            float4 hv = *(const float4*)(hp + 4 * k4);
            float4 wv = __ldg((const float4*)wp + k4);
            a = fmaf(hv.x, wv.x, a);
            a = fmaf(hv.y, wv.y, a);
            a = fmaf(hv.z, wv.z, a);
            a = fmaf(hv.w, wv.w, a);
        }
        fin_s[b * 5 + o] = a;
    }
    __syncthreads();

    // ============ Decode + output ============
    if (tid < 32) {
        int b = tid;
        float4 bx = __ldg((const float4*)p.boxes + (box0 + b));
        float cx = (bx.x + bx.z) * 0.5f, cy = (bx.y + bx.w) * 0.5f;
        float wd = bx.z - bx.x, hg = bx.w - bx.y;
        float ncx = cx + fin_s[b * 5 + 0];
        float ncy = cy + fin_s[b * 5 + 1];
        float nw = wd * __expf(fin_s[b * 5 + 2]);
        float nh = hg * __expf(fin_s[b * 5 + 3]);
        float conf = __fdividef(1.0f, 1.0f + __expf(-fin_s[b * 5 + 4]));
        float* op = p.out + (box0 + b) * 5;
        op[0] = ncx - nw * 0.5f;
        op[1] = ncy - nh * 0.5f;
        op[2] = ncx + nw * 0.5f;
        op[3] = ncy + nh * 0.5f;
        op[4] = conf;
    }
}

extern "C" void kernel_launch(void* const* d_in, const int* in_sizes, int n_in,
                              void* d_out, int out_size) {
    (void)in_sizes; (void)n_in; (void)out_size;
    Params p;
    p.mv       = (const float*)d_in[0];
    p.boxes    = (const float*)d_in[1];
    p.W_stats  = (const float*)d_in[2];
    p.b_stats  = (const float*)d_in[3];
    p.g_stats  = (const float*)d_in[4];
    p.be_stats = (const float*)d_in[5];
    p.W_b1     = (const float*)d_in[6];
    p.b_b1     = (const float*)d_in[7];
    p.g_b1     = (const float*)d_in[8];
    p.be_b1    = (const float*)d_in[9];
    p.W_b2     = (const float*)d_in[10];
    p.b_b2     = (const float*)d_in[11];
    p.g_b2     = (const float*)d_in[12];
    p.be_b2    = (const float*)d_in[13];
    p.W_ih     = (const float*)d_in[14];
    p.W_hh     = (const float*)d_in[15];
    p.b_ih     = (const float*)d_in[16];
    p.b_hh     = (const float*)d_in[17];
    p.W_p1     = (const float*)d_in[18];
    p.b_p1     = (const float*)d_in[19];
    p.W_p2     = (const float*)d_in[20];
    p.b_p2     = (const float*)d_in[21];
    p.W_s1     = (const float*)d_in[22];
    p.b_s1     = (const float*)d_in[23];
    p.W_s2     = (const float*)d_in[24];
    p.b_s2     = (const float*)d_in[25];
    p.W_c1     = (const float*)d_in[26];
    p.b_c1     = (const float*)d_in[27];
    p.W_c2     = (const float*)d_in[28];
    p.b_c2     = (const float*)d_in[29];
    p.out      = (float*)d_out;

    prep_kernel<<<128, 256>>>(p);
    cudaFuncSetAttribute(tracker_fused_kernel,
                         cudaFuncAttributeMaxDynamicSharedMemorySize, SMEM_BYTES);
    tracker_fused_kernel<<<128, NT, SMEM_BYTES>>>(p);
}